// round 16
// baseline (speedup 1.0000x reference)
#include <cuda_runtime.h>
#include <cuda_fp16.h>
#include <cstdint>

#define OUT_F 2048
#define IN_F  2048
#define NNZ   209715
#define T_TOK 16384

// ---------------------------------------------------------------------------
// Scratch: fp16 reconstructed W only (X is converted inside the GEMM now).
// ---------------------------------------------------------------------------
__device__ __half g_Wh[OUT_F * IN_F];           //  8 MB
__device__ unsigned g_dq_done;                  // dequant-blocks-finished counter

__device__ __forceinline__ uint32_t smem_u32(const void* p) {
    uint32_t a;
    asm("{ .reg .u64 t; cvta.to.shared.u64 t, %1; cvt.u32.u64 %0, t; }"
        : "=r"(a) : "l"(p));
    return a;
}

#define CP_ASYNC16(dst, src) \
    asm volatile("cp.async.cg.shared.global [%0], [%1], 16;" \
                 :: "r"((uint32_t)(dst)), "l"(src) : "memory")
#define CP_COMMIT() asm volatile("cp.async.commit_group;" ::: "memory")
#define CP_WAITN(n) asm volatile("cp.async.wait_group %0;" :: "n"(n) : "memory")

// SW128 swizzle on byte offsets (128B rows, 1024B atoms)
#define SWZ(o) ((o) ^ (((o) >> 3) & 0x70))

__device__ __forceinline__ void ldmatrix_x4(uint32_t* r, uint32_t addr) {
    asm volatile("ldmatrix.sync.aligned.m8n8.x4.shared.b16 {%0,%1,%2,%3}, [%4];"
                 : "=r"(r[0]), "=r"(r[1]), "=r"(r[2]), "=r"(r[3]) : "r"(addr));
}

__device__ __forceinline__ void mma_16816(float* c, const uint32_t* a,
                                          const uint32_t* b) {
    asm volatile(
        "mma.sync.aligned.m16n8k16.row.col.f32.f16.f16.f32 "
        "{%0,%1,%2,%3}, {%4,%5,%6,%7}, {%8,%9}, {%0,%1,%2,%3};"
        : "+f"(c[0]), "+f"(c[1]), "+f"(c[2]), "+f"(c[3])
        : "r"(a[0]), "r"(a[1]), "r"(a[2]), "r"(a[3]), "r"(b[0]), "r"(b[1]));
}

#define STS128(addr, v) \
    asm volatile("st.shared.v4.b32 [%0], {%1,%2,%3,%4};" \
                 :: "r"((uint32_t)(addr)), "r"((v).x), "r"((v).y), \
                    "r"((v).z), "r"((v).w) : "memory")

// ---------------------------------------------------------------------------
// Kernel 1 (prep): grid = [dequant | scatter] only — X conversion removed.
// ---------------------------------------------------------------------------
#define DQ_N4     (OUT_F * (IN_F / 2) / 4)     // 524288 int4-groups
#define DQ_BLOCKS (DQ_N4 / 256)                // 2048
#define SC_BLOCKS ((NNZ + 255) / 256)          // 820

__global__ void prep_kernel(const int* __restrict__ packed,
                            const float* __restrict__ scales,
                            const float* __restrict__ vals,
                            const int* __restrict__ rows,
                            const int* __restrict__ cols) {
    if (blockIdx.x < DQ_BLOCKS) {
        int idx = blockIdx.x * 256 + threadIdx.x;          // int4-group index
        int o = idx >> 8;                                  // / (IN_F/8)
        int4 v = reinterpret_cast<const int4*>(packed)[idx];
        float s = scales[o];
        __half2 h[4];
        h[0] = __floats2half2_rn((float)((v.x & 0xF) - 8) * s,
                                 (float)(((v.x >> 4) & 0xF) - 8) * s);
        h[1] = __floats2half2_rn((float)((v.y & 0xF) - 8) * s,
                                 (float)(((v.y >> 4) & 0xF) - 8) * s);
        h[2] = __floats2half2_rn((float)((v.z & 0xF) - 8) * s,
                                 (float)(((v.z >> 4) & 0xF) - 8) * s);
        h[3] = __floats2half2_rn((float)((v.w & 0xF) - 8) * s,
                                 (float)(((v.w >> 4) & 0xF) - 8) * s);
        reinterpret_cast<uint4*>(g_Wh)[idx] = *reinterpret_cast<uint4*>(h);
        __syncthreads();
        if (threadIdx.x == 0) {
            __threadfence();
            atomicAdd(&g_dq_done, 1u);
        }
    } else {
        if (threadIdx.x == 0) {
            volatile unsigned* flag = &g_dq_done;
            while (*flag < DQ_BLOCKS) {
                asm volatile("nanosleep.u32 64;");
            }
        }
        __syncthreads();
        __threadfence();
        int i = (blockIdx.x - DQ_BLOCKS) * 256 + threadIdx.x;
        if (i < NNZ)
            atomicAdd(&g_Wh[(size_t)rows[i] * IN_F + cols[i]],
                      __float2half(vals[i]));
    }
}

// ---------------------------------------------------------------------------
// Kernel 2: fp16 HMMA GEMM.  CTA 128x128, BK=64, 3-stage, 4 warps of 64x64.
// A path: LDG fp32 from original x -> convert -> STS fp16 (swizzled),
// pipelined 2 stages ahead in two half-batches per iteration.
// B path: cp.async from fp16 g_Wh (unchanged).
// Fragment register double-buffering removed (proven neutral in R7) to pay
// for the 32 A-staging registers.
// ---------------------------------------------------------------------------
#define MT 128
#define NT 128
#define BK 64
#define NSTAGE 3
#define STAGE_BYTES 32768u
#define A_OFF(s) ((s) * STAGE_BYTES)
#define B_OFF(s) (A_OFF(s) + 16384u)
#define GEMM_SMEM (NSTAGE * STAGE_BYTES)   // 98304

// Load half h (4 fp16-chunks) of an A stage as fp32 into st4[8].
__device__ __forceinline__ void ldgA_half(float4* st4, const float* Xb32,
                                          int tid, int k0, int h) {
    #pragma unroll
    for (int j = 0; j < 4; j++) {
        int item = tid + (h * 4 + j) * 128;
        int row = item >> 3, seg = item & 7;
        const float* src = Xb32 + (size_t)row * IN_F + k0 + seg * 8;
        st4[2 * j]     = *reinterpret_cast<const float4*>(src);
        st4[2 * j + 1] = *reinterpret_cast<const float4*>(src + 4);
    }
}

// Convert st4 -> fp16 and store into A stage s (swizzled).
__device__ __forceinline__ void stsA_half(const float4* st4, uint32_t sb,
                                          int tid, int s, int h) {
    #pragma unroll
    for (int j = 0; j < 4; j++) {
        int item = tid + (h * 4 + j) * 128;
        int row = item >> 3, seg = item & 7;
        __half2 hh[4];
        hh[0] = __floats2half2_rn(st4[2 * j].x,     st4[2 * j].y);
        hh[1] = __floats2half2_rn(st4[2 * j].z,     st4[2 * j].w);
        hh[2] = __floats2half2_rn(st4[2 * j + 1].x, st4[2 * j + 1].y);
        hh[3] = __floats2half2_rn(st4[2 * j + 1].z, st4[2 * j + 1].w);
        uint4 u = *reinterpret_cast<uint4*>(hh);
        STS128(sb + A_OFF(s) + SWZ(row * 128 + seg * 16), u);
    }
}

__device__ __forceinline__ void loadB_stage(uint32_t sb, int tid,
                                            const __half* Wb, int k0, int s) {
    #pragma unroll
    for (int j = 0; j < 8; j++) {
        int item = tid + j * 128;
        int row = item >> 3, ck = item & 7;
        CP_ASYNC16(sb + B_OFF(s) + SWZ(row * 128 + ck * 16),
                   Wb + (size_t)row * IN_F + k0 + ck * 8);
    }
    CP_COMMIT();
}

__device__ __forceinline__ void load_frags(uint32_t sA, uint32_t sB,
                                           int wm, int wn, int lane, int kslot,
                                           uint32_t af[4][4], uint32_t bf[8][2]) {
    const int ckb = kslot * 2;
    #pragma unroll
    for (int mt = 0; mt < 4; mt++) {
        int row = wm + mt * 16 + (lane & 7) + ((lane >> 3) & 1) * 8;
        int ck  = ckb + ((lane >> 4) & 1);
        ldmatrix_x4(af[mt], sA + SWZ(row * 128 + ck * 16));
    }
    #pragma unroll
    for (int np = 0; np < 4; np++) {
        int sel = lane >> 3;
        int row = wn + np * 16 + (sel >> 1) * 8 + (lane & 7);
        int ck  = ckb + (sel & 1);
        uint32_t r[4];
        ldmatrix_x4(r, sB + SWZ(row * 128 + ck * 16));
        bf[np * 2 + 0][0] = r[0]; bf[np * 2 + 0][1] = r[1];
        bf[np * 2 + 1][0] = r[2]; bf[np * 2 + 1][1] = r[3];
    }
}

__global__ __launch_bounds__(128, 2) void gemm_hmma(const float* __restrict__ X,
                                                    float* __restrict__ C) {
    extern __shared__ char smem[];
    const uint32_t sb = smem_u32(smem);
    const int tid  = threadIdx.x;
    const int wid  = tid >> 5;
    const int lane = tid & 31;

    if (blockIdx.x == 0 && blockIdx.y == 0 && tid == 0) g_dq_done = 0;

    const int m0 = blockIdx.y * MT;
    const int n0 = blockIdx.x * NT;
    const int wm = (wid & 1) * 64;
    const int wn = (wid >> 1) * 64;

    const float*  Xb32 = X    + (size_t)m0 * IN_F;
    const __half* Wb   = g_Wh + (size_t)n0 * IN_F;

    float acc[4][8][4];
    #pragma unroll
    for (int i = 0; i < 4; i++)
        #pragma unroll
        for (int j = 0; j < 8; j++)
            #pragma unroll
            for (int q = 0; q < 4; q++) acc[i][j][q] = 0.0f;

    float4 st4[8];   // A staging (32 regs)

    // Prologue: B stages 0,1 via cp.async; A stages 0,1 via LDG+CVT+STS.
    loadB_stage(sb, tid, Wb, 0, 0);
    loadB_stage(sb, tid, Wb, BK, 1);
    #pragma unroll
    for (int s = 0; s < 2; s++) {
        ldgA_half(st4, Xb32, tid, s * BK, 0);
        stsA_half(st4, sb, tid, s, 0);
        ldgA_half(st4, Xb32, tid, s * BK, 1);
        stsA_half(st4, sb, tid, s, 1);
    }

    uint32_t af[4][4];
    uint32_t bf[8][2];

    const int NIT = IN_F / BK;   // 32
    for (int k = 0; k < NIT; k++) {
        if (k + 1 < NIT) CP_WAITN(1); else CP_WAITN(0);
        __syncthreads();   // stage k visible; stage (k+2)%3 free for refill

        const bool pf = (k + 2 < NIT);
        const int  k2 = (k + 2) * BK;
        const int  s2 = (k + 2) % NSTAGE;
        if (pf) {
            loadB_stage(sb, tid, Wb, k2, s2);
            ldgA_half(st4, Xb32, tid, k2, 0);
        }

        const int st = k % NSTAGE;
        const uint32_t sA = sb + A_OFF(st);
        const uint32_t sB = sb + B_OFF(st);

        #pragma unroll
        for (int ks = 0; ks < BK / 16; ks++) {
            load_frags(sA, sB, wm, wn, lane, ks, af, bf);
            #pragma unroll
            for (int mt = 0; mt < 4; mt++)
                #pragma unroll
                for (int nt = 0; nt < 8; nt++)
                    mma_16816(acc[mt][nt], af[mt], bf[nt]);
            if (ks == 1 && pf) {
                stsA_half(st4, sb, tid, s2, 0);
                ldgA_half(st4, Xb32, tid, k2, 1);
            } else if (ks == 2 && pf) {
                stsA_half(st4, sb, tid, s2, 1);
            }
        }
    }

    #pragma unroll
    for (int mt = 0; mt < 4; mt++) {
        #pragma unroll
        for (int nt = 0; nt < 8; nt++) {
            int m = m0 + wm + mt * 16 + (lane >> 2);
            int n = n0 + wn + nt * 8 + (lane & 3) * 2;
            float2* p0 = reinterpret_cast<float2*>(C + (size_t)m * OUT_F + n);
            float2* p1 = reinterpret_cast<float2*>(C + (size_t)(m + 8) * OUT_F + n);
            *p0 = make_float2(acc[mt][nt][0], acc[mt][nt][1]);
            *p1 = make_float2(acc[mt][nt][2], acc[mt][nt][3]);
        }
    }
}

// ---------------------------------------------------------------------------
// Launch: prep (dequant+scatter) -> GEMM (with inline X conversion)
// ---------------------------------------------------------------------------
extern "C" void kernel_launch(void* const* d_in, const int* in_sizes, int n_in,
                              void* d_out, int out_size) {
    const float* x      = (const float*)d_in[0];
    const int*   packed = (const int*)  d_in[1];
    const float* scales = (const float*)d_in[2];
    const float* o_vals = (const float*)d_in[3];
    const int*   o_rows = (const int*)  d_in[4];
    const int*   o_cols = (const int*)  d_in[5];
    float*       out    = (float*)d_out;

    cudaFuncSetAttribute(gemm_hmma,
                         cudaFuncAttributeMaxDynamicSharedMemorySize, GEMM_SMEM);

    prep_kernel<<<DQ_BLOCKS + SC_BLOCKS, 256>>>(
        packed, scales, o_vals, o_rows, o_cols);
    {
        dim3 grid(OUT_F / NT, T_TOK / MT);   // (16, 128)
        gemm_hmma<<<grid, 128, GEMM_SMEM>>>(x, out);
    }
}